// round 3
// baseline (speedup 1.0000x reference)
#include <cuda_runtime.h>
#include <math.h>

#define T_TOK 2048
#define D_DIM 1024
#define F_DIM 2048
#define NE 8

// ---- scratch (no device allocs allowed) ----
__device__ float g_H[(size_t)T_TOK * F_DIM];   // silu(gate)*up; shared path (token order), then routed (grouped order)
__device__ int   g_tok_e[T_TOK];               // per-token expert
__device__ float g_tok_s[T_TOK];               // per-token sigmoid score
__device__ int   g_order[T_TOK];               // grouped row -> token
__device__ int   g_offs[NE + 1];               // expert segment offsets

__device__ __forceinline__ float silu_f(float x) { return x / (1.0f + expf(-x)); }

// ---------------- router: ONE THREAD per token, fully serial (no warp intrinsics) ----------------
__global__ void router_kernel(const float* __restrict__ x, const float* __restrict__ rw) {
    int t = blockIdx.x * blockDim.x + threadIdx.x;
    if (t >= T_TOK) return;
    const float4* xr = (const float4*)(x + (size_t)t * D_DIM);
    float best = -1e30f; int be = 0;
#pragma unroll
    for (int e = 0; e < NE; e++) {
        const float4* wr = (const float4*)(rw + (size_t)e * D_DIM);
        float s = 0.f;
        for (int i = 0; i < D_DIM / 4; i++) {
            float4 a = xr[i], b = wr[i];
            s += a.x * b.x + a.y * b.y + a.z * b.z + a.w * b.w;
        }
        if (s > best) { best = s; be = e; }   // first-max tie-break (matches top_k)
    }
    g_tok_e[t] = be;
    g_tok_s[t] = 1.0f / (1.0f + expf(-best));
}

// ---------------- brute-force stable rank: row(t) = #{u : e_u < e_t or (e_u==e_t and u<t)} ----------------
__global__ void rank_kernel() {
    int t = blockIdx.x * blockDim.x + threadIdx.x;
    if (t >= T_TOK) return;
    int e = g_tok_e[t];
    int r = 0;
    for (int u = 0; u < T_TOK; u++) {
        int eu = g_tok_e[u];
        r += (eu < e) || (eu == e && u < t);
    }
    g_order[r] = t;
}

__global__ void offs_kernel() {
    int e = threadIdx.x;
    if (e > NE) return;
    int c = 0;
    for (int u = 0; u < T_TOK; u++) c += (g_tok_e[u] < e);
    g_offs[e] = c;     // offs[0]=0 ... offs[NE]=T
}

// ---------------- fused gate+up GEMM: H = silu(A@Bg) * (A@Bu) ----------------
// BM=128, BN=64, BK=8, 256 threads, TM=8 x TN=4, dual accumulators.
// GATHER: A rows are hidden[g_order[seg_start+row]] * g_tok_s[token] (no Xe buffer).
template <bool GATHER>
__global__ void gemm_gateup(const float* __restrict__ X,
                            const float* __restrict__ Bg_base,
                            const float* __restrict__ Bu_base,
                            size_t Bstride, float* __restrict__ Hbase,
                            int K, int N) {
    const int BM = 128, BN = 64, BK = 8, TM = 8, TN = 4;
    int e = blockIdx.z;
    int seg_start = 0, seg_rows = T_TOK;
    if (GATHER) { seg_start = g_offs[e]; seg_rows = g_offs[e + 1] - seg_start; }
    int row0 = blockIdx.y * BM;
    if (row0 >= seg_rows) return;
    const float* Bg = Bg_base + (size_t)e * Bstride;
    const float* Bu = Bu_base + (size_t)e * Bstride;
    float* H = Hbase + (size_t)seg_start * N;
    int col0 = blockIdx.x * BN;

    __shared__ float As[BK][BM];
    __shared__ float Bgs[BK][BN];
    __shared__ float Bus[BK][BN];

    int tid = threadIdx.x;
    int rowA = tid >> 1, kA = (tid & 1) * 4;     // A: 128 rows x 8k, one float4/thread
    int half = tid >> 7;                          // 0: gate tile, 1: up tile
    int t2 = tid & 127;
    int kB = t2 >> 4;                             // 0..7
    int colB = (t2 & 15) * 4;                     // 0..60
    int tx = tid & 15, ty = tid >> 4;

    float accg[TM][TN] = {}, accu[TM][TN] = {};
    float ra[TM], rg[TN], ru[TN];

    bool aValid = (row0 + rowA) < seg_rows;
    float scale = 1.0f;
    const float* Aptr;
    if (GATHER) {
        int tok = aValid ? g_order[seg_start + row0 + rowA] : 0;
        scale = aValid ? g_tok_s[tok] : 0.0f;
        Aptr = X + (size_t)tok * K + kA;
    } else {
        Aptr = X + (size_t)(row0 + rowA) * K + kA;
    }
    const float* BgPtr = Bg + (size_t)kB * N + col0 + colB;
    const float* BuPtr = Bu + (size_t)kB * N + col0 + colB;

    for (int k0 = 0; k0 < K; k0 += BK) {
        float4 av = aValid ? *(const float4*)Aptr : make_float4(0.f, 0.f, 0.f, 0.f);
        if (GATHER) { av.x *= scale; av.y *= scale; av.z *= scale; av.w *= scale; }
        As[kA + 0][rowA] = av.x; As[kA + 1][rowA] = av.y;
        As[kA + 2][rowA] = av.z; As[kA + 3][rowA] = av.w;
        if (half == 0) *(float4*)&Bgs[kB][colB] = *(const float4*)BgPtr;
        else           *(float4*)&Bus[kB][colB] = *(const float4*)BuPtr;
        __syncthreads();
#pragma unroll
        for (int k = 0; k < BK; k++) {
            *(float4*)&ra[0] = *(const float4*)&As[k][ty * TM];
            *(float4*)&ra[4] = *(const float4*)&As[k][ty * TM + 4];
            *(float4*)&rg[0] = *(const float4*)&Bgs[k][tx * TN];
            *(float4*)&ru[0] = *(const float4*)&Bus[k][tx * TN];
#pragma unroll
            for (int i = 0; i < TM; i++)
#pragma unroll
                for (int j = 0; j < TN; j++) {
                    accg[i][j] += ra[i] * rg[j];
                    accu[i][j] += ra[i] * ru[j];
                }
        }
        __syncthreads();
        Aptr += BK; BgPtr += (size_t)BK * N; BuPtr += (size_t)BK * N;
    }

#pragma unroll
    for (int i = 0; i < TM; i++) {
        int r = row0 + ty * TM + i;
        if (r >= seg_rows) break;
        size_t base = (size_t)r * N + col0 + tx * TN;
        float4 h;
        h.x = silu_f(accg[i][0]) * accu[i][0];
        h.y = silu_f(accg[i][1]) * accu[i][1];
        h.z = silu_f(accg[i][2]) * accu[i][2];
        h.w = silu_f(accg[i][3]) * accu[i][3];
        *(float4*)(H + base) = h;
    }
}

// ---------------- down GEMM. SCATTER: out[g_order[row]] += acc (routed). else out[row] = acc ----------------
template <bool SCATTER>
__global__ void gemm_down(const float* __restrict__ Abase, const float* __restrict__ Bbase,
                          size_t Bstride, float* __restrict__ out, int M, int K, int N) {
    const int BM = 128, BN = 128, BK = 8, TM = 8, TN = 8;
    int e = blockIdx.z;
    int seg_start = 0, seg_rows = M;
    if (SCATTER) { seg_start = g_offs[e]; seg_rows = g_offs[e + 1] - seg_start; }
    int row0 = blockIdx.y * BM;
    if (row0 >= seg_rows) return;
    const float* A = Abase + (size_t)seg_start * K;
    const float* B = Bbase + (size_t)e * Bstride;
    int col0 = blockIdx.x * BN;

    __shared__ float As[BK][BM];
    __shared__ float Bs[BK][BN];

    int tid = threadIdx.x;
    int rowA = tid >> 1, kA = (tid & 1) * 4;
    int kB = tid >> 5, colB = (tid & 31) * 4;
    int tx = tid & 15, ty = tid >> 4;

    float acc[TM][TN] = {};
    float ra[TM], rb[TN];

    bool aValid = (row0 + rowA) < seg_rows;
    const float* Aptr = A + (size_t)(row0 + rowA) * K + kA;
    const float* Bptr = B + (size_t)kB * N + col0 + colB;

    for (int k0 = 0; k0 < K; k0 += BK) {
        float4 av = aValid ? *(const float4*)Aptr : make_float4(0.f, 0.f, 0.f, 0.f);
        As[kA + 0][rowA] = av.x; As[kA + 1][rowA] = av.y;
        As[kA + 2][rowA] = av.z; As[kA + 3][rowA] = av.w;
        *(float4*)&Bs[kB][colB] = *(const float4*)Bptr;
        __syncthreads();
#pragma unroll
        for (int k = 0; k < BK; k++) {
            *(float4*)&ra[0] = *(const float4*)&As[k][ty * TM];
            *(float4*)&ra[4] = *(const float4*)&As[k][ty * TM + 4];
            *(float4*)&rb[0] = *(const float4*)&Bs[k][tx * TN];
            *(float4*)&rb[4] = *(const float4*)&Bs[k][tx * TN + 4];
#pragma unroll
            for (int i = 0; i < TM; i++)
#pragma unroll
                for (int j = 0; j < TN; j++) acc[i][j] += ra[i] * rb[j];
        }
        __syncthreads();
        Aptr += BK; Bptr += (size_t)BK * N;
    }

#pragma unroll
    for (int i = 0; i < TM; i++) {
        int r = row0 + ty * TM + i;
        if (r >= seg_rows) break;
        size_t obase;
        if (SCATTER) {
            int tok = g_order[seg_start + r];
            obase = (size_t)tok * N + col0 + tx * TN;
        } else {
            obase = (size_t)r * N + col0 + tx * TN;
        }
#pragma unroll
        for (int j = 0; j < TN; j += 4) {
            float4 v = make_float4(acc[i][j], acc[i][j + 1], acc[i][j + 2], acc[i][j + 3]);
            if (SCATTER) {
                float4 o = *(const float4*)(out + obase + j);
                v.x += o.x; v.y += o.y; v.z += o.z; v.w += o.w;
            }
            *(float4*)(out + obase + j) = v;
        }
    }
}

extern "C" void kernel_launch(void* const* d_in, const int* in_sizes, int n_in,
                              void* d_out, int out_size) {
    const float* hidden   = (const float*)d_in[0];
    const float* router_w = (const float*)d_in[1];
    const float* w_gate   = (const float*)d_in[2];
    const float* w_up     = (const float*)d_in[3];
    const float* w_down   = (const float*)d_in[4];
    const float* ws_gate  = (const float*)d_in[5];
    const float* ws_up    = (const float*)d_in[6];
    const float* ws_down  = (const float*)d_in[7];
    float* out = (float*)d_out;

    // routing metadata (fully brute-force, deterministic)
    router_kernel<<<T_TOK / 256, 256>>>(hidden, router_w);
    rank_kernel<<<T_TOK / 256, 256>>>();
    offs_kernel<<<1, 32>>>();

    // shared expert: H = silu(X@ws_gate)*(X@ws_up) ; out = H@ws_down
    dim3 gridSg(F_DIM / 64, T_TOK / 128, 1);
    gemm_gateup<false><<<gridSg, 256>>>(hidden, ws_gate, ws_up, 0, g_H, D_DIM, F_DIM);
    dim3 gridSd(D_DIM / 128, T_TOK / 128, 1);
    gemm_down<false><<<gridSd, 256>>>(g_H, ws_down, 0, out, T_TOK, F_DIM, D_DIM);

    // routed experts (grouped, A gathered from hidden with score scaling):
    // H = silu((s*x)@Wg[e]) * ((s*x)@Wu[e]) ; out[token] += H@Wd[e]
    dim3 gridRg(F_DIM / 64, T_TOK / 128, NE);
    gemm_gateup<true><<<gridRg, 256>>>(hidden, w_gate, w_up, (size_t)D_DIM * F_DIM, g_H, D_DIM, F_DIM);
    dim3 gridRd(D_DIM / 128, T_TOK / 128, NE);
    gemm_down<true><<<gridRd, 256>>>(g_H, w_down, (size_t)F_DIM * D_DIM, out, T_TOK, F_DIM, D_DIM);

    (void)in_sizes; (void)n_in; (void)out_size;
}

// round 4
// speedup vs baseline: 1.0195x; 1.0195x over previous
#include <cuda_runtime.h>
#include <math.h>

#define T_TOK 2048
#define D_DIM 1024
#define F_DIM 2048
#define NE 8

// ---- scratch (no device allocs allowed) ----
__device__ float g_H[(size_t)T_TOK * F_DIM];   // silu(gate)*up
__device__ int   g_tok_e[T_TOK];
__device__ float g_tok_s[T_TOK];
__device__ int   g_order[T_TOK];               // grouped row -> token
__device__ int   g_offs[NE + 1];

__device__ __forceinline__ float silu_f(float x) { return x / (1.0f + expf(-x)); }

// ---------------- router: one block per token, coalesced, deterministic tree reduce ----------------
__global__ void router_kernel(const float* __restrict__ x, const float* __restrict__ rw) {
    __shared__ float red[256][NE + 1];          // +1 pad kills bank conflicts
    int t = blockIdx.x, tid = threadIdx.x;
    float4 xa = ((const float4*)(x + (size_t)t * D_DIM))[tid];   // 256*4 = 1024 = D
#pragma unroll
    for (int e = 0; e < NE; e++) {
        float4 wv = ((const float4*)(rw + (size_t)e * D_DIM))[tid];
        red[tid][e] = xa.x * wv.x + xa.y * wv.y + xa.z * wv.z + xa.w * wv.w;
    }
    __syncthreads();
    for (int s = 128; s > 0; s >>= 1) {
        if (tid < s)
#pragma unroll
            for (int e = 0; e < NE; e++) red[tid][e] += red[tid + s][e];
        __syncthreads();
    }
    if (tid == 0) {
        float bv = red[0][0]; int be = 0;
#pragma unroll
        for (int e = 1; e < NE; e++) if (red[0][e] > bv) { bv = red[0][e]; be = e; }
        g_tok_e[t] = be;
        g_tok_s[t] = 1.0f / (1.0f + expf(-bv));
    }
}

// ---------------- brute-force stable rank (proven correct in R3, ~us scale) ----------------
__global__ void rank_kernel() {
    int t = blockIdx.x * blockDim.x + threadIdx.x;
    if (t >= T_TOK) return;
    int e = g_tok_e[t];
    int r = 0;
    for (int u = 0; u < T_TOK; u++) {
        int eu = g_tok_e[u];
        r += (eu < e) || (eu == e && u < t);
    }
    g_order[r] = t;
}

__global__ void offs_kernel() {
    int e = threadIdx.x;
    if (e > NE) return;
    int c = 0;
    for (int u = 0; u < T_TOK; u++) c += (g_tok_e[u] < e);
    g_offs[e] = c;
}

// ---------------- fused gate+up GEMM, double-buffered, BK=16 ----------------
// BM=128, BN=64, 256 threads, per-thread 8x4 gate + 8x4 up accumulators.
// GATHER: A rows gathered from hidden via g_order, scaled by g_tok_s.
template <bool GATHER>
__global__ void __launch_bounds__(256, 2)
gemm_gateup(const float* __restrict__ X,
            const float* __restrict__ Bg_base,
            const float* __restrict__ Bu_base,
            size_t Bstride, float* __restrict__ Hbase,
            int K, int N) {
    const int BM = 128, BN = 64, BK = 16, TM = 8, TN = 4;
    const int LDA = BM + 4;
    int e = blockIdx.z;
    int seg_start = 0, seg_rows = T_TOK;
    if (GATHER) { seg_start = g_offs[e]; seg_rows = g_offs[e + 1] - seg_start; }
    int row0 = blockIdx.y * BM;
    if (row0 >= seg_rows) return;
    const float* Bg = Bg_base + (size_t)e * Bstride;
    const float* Bu = Bu_base + (size_t)e * Bstride;
    float* H = Hbase + (size_t)seg_start * N;
    int col0 = blockIdx.x * BN;

    __shared__ float As[2][BK][LDA];     // 16.5KB
    __shared__ float Bgs[2][BK][BN];     // 8KB
    __shared__ float Bus[2][BK][BN];     // 8KB

    int tid = threadIdx.x;
    int tx = tid & 15, ty = tid >> 4;

    // A: 128 rows x 16 k = 512 float4; 2 per thread
    int arow[2], akq[2]; const float* abase[2]; float ascale[2]; bool avalid[2];
#pragma unroll
    for (int i = 0; i < 2; i++) {
        int f4 = i * 256 + tid;
        arow[i] = f4 >> 2; akq[i] = (f4 & 3) * 4;
        int r = row0 + arow[i];
        avalid[i] = r < seg_rows;
        if (GATHER) {
            int tok = avalid[i] ? g_order[seg_start + r] : 0;
            ascale[i] = avalid[i] ? g_tok_s[tok] : 0.0f;
            abase[i] = X + (size_t)tok * K + akq[i];
        } else {
            ascale[i] = 1.0f;
            abase[i] = X + (size_t)(avalid[i] ? r : 0) * K + akq[i];
        }
    }
    // B: each half of the block loads one matrix; 16x64 = 256 float4 per matrix; 2 per thread
    int half = tid >> 7, t2 = tid & 127;
    int bk[2], bcol[2]; const float* bbase[2];
#pragma unroll
    for (int i = 0; i < 2; i++) {
        int f4 = i * 128 + t2;
        bk[i] = f4 >> 4; bcol[i] = (f4 & 15) * 4;
        bbase[i] = (half ? Bu : Bg) + (size_t)bk[i] * N + col0 + bcol[i];
    }

    float accg[TM][TN] = {}, accu[TM][TN] = {};
    float ra[TM], rg[TN], ru[TN];
    int nTiles = K / BK;

    // prologue: stage 0
    {
#pragma unroll
        for (int i = 0; i < 2; i++) {
            float4 av = avalid[i] ? *(const float4*)abase[i] : make_float4(0.f,0.f,0.f,0.f);
            av.x *= ascale[i]; av.y *= ascale[i]; av.z *= ascale[i]; av.w *= ascale[i];
            As[0][akq[i]+0][arow[i]] = av.x; As[0][akq[i]+1][arow[i]] = av.y;
            As[0][akq[i]+2][arow[i]] = av.z; As[0][akq[i]+3][arow[i]] = av.w;
            float4 bv = *(const float4*)bbase[i];
            if (half == 0) *(float4*)&Bgs[0][bk[i]][bcol[i]] = bv;
            else           *(float4*)&Bus[0][bk[i]][bcol[i]] = bv;
        }
    }
    __syncthreads();

    for (int tile = 0; tile < nTiles - 1; tile++) {
        int buf = tile & 1;
        // prefetch next tile into registers
        float4 apre[2], bpre[2];
#pragma unroll
        for (int i = 0; i < 2; i++) {
            apre[i] = avalid[i] ? *(const float4*)(abase[i] + (size_t)(tile + 1) * BK)
                                : make_float4(0.f,0.f,0.f,0.f);
            bpre[i] = *(const float4*)(bbase[i] + (size_t)(tile + 1) * BK * N);
        }
        // compute current buffer
#pragma unroll
        for (int k = 0; k < BK; k++) {
            *(float4*)&ra[0] = *(const float4*)&As[buf][k][ty * TM];
            *(float4*)&ra[4] = *(const float4*)&As[buf][k][ty * TM + 4];
            *(float4*)&rg[0] = *(const float4*)&Bgs[buf][k][tx * TN];
            *(float4*)&ru[0] = *(const float4*)&Bus[buf][k][tx * TN];
#pragma unroll
            for (int i = 0; i < TM; i++)
#pragma unroll
                for (int j = 0; j < TN; j++) {
                    accg[i][j] += ra[i] * rg[j];
                    accu[i][j] += ra[i] * ru[j];
                }
        }
        // store prefetched into other buffer
#pragma unroll
        for (int i = 0; i < 2; i++) {
            float4 av = apre[i];
            av.x *= ascale[i]; av.y *= ascale[i]; av.z *= ascale[i]; av.w *= ascale[i];
            As[buf^1][akq[i]+0][arow[i]] = av.x; As[buf^1][akq[i]+1][arow[i]] = av.y;
            As[buf^1][akq[i]+2][arow[i]] = av.z; As[buf^1][akq[i]+3][arow[i]] = av.w;
            if (half == 0) *(float4*)&Bgs[buf^1][bk[i]][bcol[i]] = bpre[i];
            else           *(float4*)&Bus[buf^1][bk[i]][bcol[i]] = bpre[i];
        }
        __syncthreads();
    }
    {   // last tile
        int buf = (nTiles - 1) & 1;
#pragma unroll
        for (int k = 0; k < BK; k++) {
            *(float4*)&ra[0] = *(const float4*)&As[buf][k][ty * TM];
            *(float4*)&ra[4] = *(const float4*)&As[buf][k][ty * TM + 4];
            *(float4*)&rg[0] = *(const float4*)&Bgs[buf][k][tx * TN];
            *(float4*)&ru[0] = *(const float4*)&Bus[buf][k][tx * TN];
#pragma unroll
            for (int i = 0; i < TM; i++)
#pragma unroll
                for (int j = 0; j < TN; j++) {
                    accg[i][j] += ra[i] * rg[j];
                    accu[i][j] += ra[i] * ru[j];
                }
        }
    }

#pragma unroll
    for (int i = 0; i < TM; i++) {
        int r = row0 + ty * TM + i;
        if (r >= seg_rows) break;
        size_t base = (size_t)r * N + col0 + tx * TN;
        float4 h;
        h.x = silu_f(accg[i][0]) * accu[i][0];
        h.y = silu_f(accg[i][1]) * accu[i][1];
        h.z = silu_f(accg[i][2]) * accu[i][2];
        h.w = silu_f(accg[i][3]) * accu[i][3];
        *(float4*)(H + base) = h;
    }
}

// ---------------- down GEMM, double-buffered, BK=16. SCATTER: out[g_order[row]] += ----------------
template <bool SCATTER>
__global__ void __launch_bounds__(256, 2)
gemm_down(const float* __restrict__ Abase, const float* __restrict__ Bbase,
          size_t Bstride, float* __restrict__ out, int M, int K, int N) {
    const int BM = 128, BN = 128, BK = 16, TM = 8, TN = 8;
    const int LDA = BM + 4;
    int e = blockIdx.z;
    int seg_start = 0, seg_rows = M;
    if (SCATTER) { seg_start = g_offs[e]; seg_rows = g_offs[e + 1] - seg_start; }
    int row0 = blockIdx.y * BM;
    if (row0 >= seg_rows) return;
    const float* A = Abase + (size_t)seg_start * K;
    const float* B = Bbase + (size_t)e * Bstride;
    int col0 = blockIdx.x * BN;

    __shared__ float As[2][BK][LDA];     // 16.5KB
    __shared__ float Bs[2][BK][BN];      // 16KB

    int tid = threadIdx.x;
    int tx = tid & 15, ty = tid >> 4;

    int arow[2], akq[2]; const float* abase2[2]; bool avalid[2];
#pragma unroll
    for (int i = 0; i < 2; i++) {
        int f4 = i * 256 + tid;
        arow[i] = f4 >> 2; akq[i] = (f4 & 3) * 4;
        int r = row0 + arow[i];
        avalid[i] = r < seg_rows;
        abase2[i] = A + (size_t)(avalid[i] ? r : 0) * K + akq[i];
    }
    int bk[2], bcol[2]; const float* bbase[2];
#pragma unroll
    for (int i = 0; i < 2; i++) {
        int f4 = i * 256 + tid;
        bk[i] = f4 >> 5; bcol[i] = (f4 & 31) * 4;
        bbase[i] = B + (size_t)bk[i] * N + col0 + bcol[i];
    }

    float acc[TM][TN] = {};
    float ra[TM], rb[TN];
    int nTiles = K / BK;

    {
#pragma unroll
        for (int i = 0; i < 2; i++) {
            float4 av = avalid[i] ? *(const float4*)abase2[i] : make_float4(0.f,0.f,0.f,0.f);
            As[0][akq[i]+0][arow[i]] = av.x; As[0][akq[i]+1][arow[i]] = av.y;
            As[0][akq[i]+2][arow[i]] = av.z; As[0][akq[i]+3][arow[i]] = av.w;
            *(float4*)&Bs[0][bk[i]][bcol[i]] = *(const float4*)bbase[i];
        }
    }
    __syncthreads();

    for (int tile = 0; tile < nTiles - 1; tile++) {
        int buf = tile & 1;
        float4 apre[2], bpre[2];
#pragma unroll
        for (int i = 0; i < 2; i++) {
            apre[i] = avalid[i] ? *(const float4*)(abase2[i] + (size_t)(tile + 1) * BK)
                                : make_float4(0.f,0.f,0.f,0.f);
            bpre[i] = *(const float4*)(bbase[i] + (size_t)(tile + 1) * BK * N);
        }
#pragma unroll
        for (int k = 0; k < BK; k++) {
            *(float4*)&ra[0] = *(const float4*)&As[buf][k][ty * TM];
            *(float4*)&ra[4] = *(const float4*)&As[buf][k][ty * TM + 4];
            *(float4*)&rb[0] = *(const float4*)&Bs[buf][k][tx * TN];
            *(float4*)&rb[4] = *(const float4*)&Bs[buf][k][tx * TN + 4];
#pragma unroll
            for (int i = 0; i < TM; i++)
#pragma unroll
                for (int j = 0; j < TN; j++) acc[i][j] += ra[i] * rb[j];
        }
#pragma unroll
        for (int i = 0; i < 2; i++) {
            As[buf^1][akq[i]+0][arow[i]] = apre[i].x; As[buf^1][akq[i]+1][arow[i]] = apre[i].y;
            As[buf^1][akq[i]+2][arow[i]] = apre[i].z; As[buf^1][akq[i]+3][arow[i]] = apre[i].w;
            *(float4*)&Bs[buf^1][bk[i]][bcol[i]] = bpre[i];
        }
        __syncthreads();
    }
    {
        int buf = (nTiles - 1) & 1;
#pragma unroll
        for (int k = 0; k < BK; k++) {
            *(float4*)&ra[0] = *(const float4*)&As[buf][k][ty * TM];
            *(float4*)&ra[4] = *(const float4*)&As[buf][k][ty * TM + 4];
            *(float4*)&rb[0] = *(const float4*)&Bs[buf][k][tx * TN];
            *(float4*)&rb[4] = *(const float4*)&Bs[buf][k][tx * TN + 4];
#pragma unroll
            for (int i = 0; i < TM; i++)
#pragma unroll
                for (int j = 0; j < TN; j++) acc[i][j] += ra[i] * rb[j];
        }
    }

#pragma unroll
    for (int i = 0; i < TM; i++) {
        int r = row0 + ty * TM + i;
        if (r >= seg_rows) break;
        size_t obase;
        if (SCATTER) {
            int tok = g_order[seg_start + r];
            obase = (size_t)tok * N + col0 + tx * TN;
        } else {
            obase = (size_t)r * N + col0 + tx * TN;
        }
#pragma unroll
        for (int j = 0; j < TN; j += 4) {
            float4 v = make_float4(acc[i][j], acc[i][j+1], acc[i][j+2], acc[i][j+3]);
            if (SCATTER) {
                float4 o = *(const float4*)(out + obase + j);
                v.x += o.x; v.y += o.y; v.z += o.z; v.w += o.w;
            }
            *(float4*)(out + obase + j) = v;
        }
    }
}

extern "C" void kernel_launch(void* const* d_in, const int* in_sizes, int n_in,
                              void* d_out, int out_size) {
    const float* hidden   = (const float*)d_in[0];
    const float* router_w = (const float*)d_in[1];
    const float* w_gate   = (const float*)d_in[2];
    const float* w_up     = (const float*)d_in[3];
    const float* w_down   = (const float*)d_in[4];
    const float* ws_gate  = (const float*)d_in[5];
    const float* ws_up    = (const float*)d_in[6];
    const float* ws_down  = (const float*)d_in[7];
    float* out = (float*)d_out;

    // routing metadata (deterministic)
    router_kernel<<<T_TOK, 256>>>(hidden, router_w);
    rank_kernel<<<T_TOK / 256, 256>>>();
    offs_kernel<<<1, 32>>>();

    // shared expert
    dim3 gridSg(F_DIM / 64, T_TOK / 128, 1);
    gemm_gateup<false><<<gridSg, 256>>>(hidden, ws_gate, ws_up, 0, g_H, D_DIM, F_DIM);
    dim3 gridSd(D_DIM / 128, T_TOK / 128, 1);
    gemm_down<false><<<gridSd, 256>>>(g_H, ws_down, 0, out, T_TOK, F_DIM, D_DIM);

    // routed experts (A gathered from hidden with score scaling)
    dim3 gridRg(F_DIM / 64, T_TOK / 128, NE);
    gemm_gateup<true><<<gridRg, 256>>>(hidden, w_gate, w_up, (size_t)D_DIM * F_DIM, g_H, D_DIM, F_DIM);
    dim3 gridRd(D_DIM / 128, T_TOK / 128, NE);
    gemm_down<true><<<gridRd, 256>>>(g_H, w_down, (size_t)F_DIM * D_DIM, out, T_TOK, F_DIM, D_DIM);

    (void)in_sizes; (void)n_in; (void)out_size;
}

// round 6
// speedup vs baseline: 2.6333x; 2.5830x over previous
#include <cuda_runtime.h>
#include <math.h>

#define T_TOK 2048
#define D_DIM 1024
#define F_DIM 2048
#define NE 8

// ---- scratch: referenced ONLY inside device code (never passed as kernel args) ----
__device__ float g_H [(size_t)T_TOK * F_DIM];   // shared-expert silu(gate)*up (token order)
__device__ float g_H2[(size_t)T_TOK * F_DIM];   // routed silu(gate)*up (grouped order)
__device__ float g_O2[(size_t)T_TOK * D_DIM];   // routed down output (token order)
__device__ int   g_tok_e[T_TOK];
__device__ float g_tok_s[T_TOK];
__device__ int   g_order[T_TOK];                // grouped row -> token (bijection, top-1)
__device__ int   g_offs[NE + 1];

__device__ __forceinline__ float silu_f(float x) { return x / (1.0f + expf(-x)); }

// ---------------- router: one block per token, coalesced, deterministic ----------------
__global__ void router_kernel(const float* __restrict__ x, const float* __restrict__ rw) {
    __shared__ float red[256][NE + 1];
    int t = blockIdx.x, tid = threadIdx.x;
    float4 xa = ((const float4*)(x + (size_t)t * D_DIM))[tid];
#pragma unroll
    for (int e = 0; e < NE; e++) {
        float4 wv = ((const float4*)(rw + (size_t)e * D_DIM))[tid];
        red[tid][e] = xa.x * wv.x + xa.y * wv.y + xa.z * wv.z + xa.w * wv.w;
    }
    __syncthreads();
    for (int s = 128; s > 0; s >>= 1) {
        if (tid < s)
#pragma unroll
            for (int e = 0; e < NE; e++) red[tid][e] += red[tid + s][e];
        __syncthreads();
    }
    if (tid == 0) {
        float bv = red[0][0]; int be = 0;
#pragma unroll
        for (int e = 1; e < NE; e++) if (red[0][e] > bv) { bv = red[0][e]; be = e; }
        g_tok_e[t] = be;
        g_tok_s[t] = 1.0f / (1.0f + expf(-bv));
    }
}

// ---------------- stable rank via smem-cached brute force (deterministic) ----------------
__global__ void rank_kernel() {
    __shared__ int s_e[T_TOK];
    int tid = threadIdx.x;
    for (int i = tid; i < T_TOK; i += 256) s_e[i] = g_tok_e[i];
    __syncthreads();
    int t = blockIdx.x * 256 + tid;
    int e = s_e[t];
    int r = 0;
#pragma unroll 4
    for (int u = 0; u < T_TOK; u++) {
        int eu = s_e[u];
        r += (eu < e) || (eu == e && u < t);
    }
    g_order[r] = t;
}

__global__ void offs_kernel() {
    __shared__ int s_e[T_TOK];
    int tid = threadIdx.x;
    for (int i = tid; i < T_TOK; i += 256) s_e[i] = g_tok_e[i];
    __syncthreads();
    if (tid <= NE) {
        int c = 0;
#pragma unroll 4
        for (int u = 0; u < T_TOK; u++) c += (s_e[u] < tid);
        g_offs[tid] = c;
    }
}

// ---------------- merged gate+up GEMM (z=0: shared -> g_H; z=1..NE: routed -> g_H2) ----------------
// BM=128, BN=64, BK=16, 256 threads, dual 8x4 accumulators, double-buffered smem.
__global__ void __launch_bounds__(256, 2)
gemm_gateup_all(const float* __restrict__ X,
                const float* __restrict__ ws_gate, const float* __restrict__ ws_up,
                const float* __restrict__ w_gate,  const float* __restrict__ w_up) {
    const int BM = 128, BN = 64, BK = 16, TM = 8, TN = 4;
    const int LDA = BM + 4;
    const int K = D_DIM, N = F_DIM;

    int z = blockIdx.z;
    bool gather = (z > 0);
    int e = z - 1;
    int seg_start = 0, seg_rows = T_TOK;
    const float *Bg, *Bu; float* Hseg;
    if (gather) {
        seg_start = g_offs[e]; seg_rows = g_offs[e + 1] - seg_start;
        Bg = w_gate + (size_t)e * D_DIM * F_DIM;
        Bu = w_up   + (size_t)e * D_DIM * F_DIM;
        Hseg = g_H2 + (size_t)seg_start * N;
    } else {
        Bg = ws_gate; Bu = ws_up; Hseg = g_H;
    }
    int row0 = blockIdx.y * BM;
    if (row0 >= seg_rows) return;
    int col0 = blockIdx.x * BN;

    __shared__ float As[2][BK][LDA];
    __shared__ float Bgs[2][BK][BN];
    __shared__ float Bus[2][BK][BN];

    int tid = threadIdx.x;
    int tx = tid & 15, ty = tid >> 4;

    int arow[2], akq[2]; const float* abase[2]; float ascale[2]; bool avalid[2];
#pragma unroll
    for (int i = 0; i < 2; i++) {
        int f4 = i * 256 + tid;
        arow[i] = f4 >> 2; akq[i] = (f4 & 3) * 4;
        int r = row0 + arow[i];
        avalid[i] = r < seg_rows;
        if (gather) {
            int tok = avalid[i] ? g_order[seg_start + r] : 0;
            ascale[i] = avalid[i] ? g_tok_s[tok] : 0.0f;
            abase[i] = X + (size_t)tok * K + akq[i];
        } else {
            ascale[i] = 1.0f;
            abase[i] = X + (size_t)(avalid[i] ? r : 0) * K + akq[i];
        }
    }
    int half = tid >> 7, t2 = tid & 127;
    int bk[2], bcol[2]; const float* bbase[2];
#pragma unroll
    for (int i = 0; i < 2; i++) {
        int f4 = i * 128 + t2;
        bk[i] = f4 >> 4; bcol[i] = (f4 & 15) * 4;
        bbase[i] = (half ? Bu : Bg) + (size_t)bk[i] * N + col0 + bcol[i];
    }

    float accg[TM][TN] = {}, accu[TM][TN] = {};
    float ra[TM], rg[TN], ru[TN];
    const int nTiles = K / BK;

    {
#pragma unroll
        for (int i = 0; i < 2; i++) {
            float4 av = avalid[i] ? *(const float4*)abase[i] : make_float4(0.f,0.f,0.f,0.f);
            av.x *= ascale[i]; av.y *= ascale[i]; av.z *= ascale[i]; av.w *= ascale[i];
            As[0][akq[i]+0][arow[i]] = av.x; As[0][akq[i]+1][arow[i]] = av.y;
            As[0][akq[i]+2][arow[i]] = av.z; As[0][akq[i]+3][arow[i]] = av.w;
            float4 bv = *(const float4*)bbase[i];
            if (half == 0) *(float4*)&Bgs[0][bk[i]][bcol[i]] = bv;
            else           *(float4*)&Bus[0][bk[i]][bcol[i]] = bv;
        }
    }
    __syncthreads();

    for (int tile = 0; tile < nTiles - 1; tile++) {
        int buf = tile & 1;
        float4 apre[2], bpre[2];
#pragma unroll
        for (int i = 0; i < 2; i++) {
            apre[i] = avalid[i] ? *(const float4*)(abase[i] + (size_t)(tile + 1) * BK)
                                : make_float4(0.f,0.f,0.f,0.f);
            bpre[i] = *(const float4*)(bbase[i] + (size_t)(tile + 1) * BK * N);
        }
#pragma unroll
        for (int k = 0; k < BK; k++) {
            *(float4*)&ra[0] = *(const float4*)&As[buf][k][ty * TM];
            *(float4*)&ra[4] = *(const float4*)&As[buf][k][ty * TM + 4];
            *(float4*)&rg[0] = *(const float4*)&Bgs[buf][k][tx * TN];
            *(float4*)&ru[0] = *(const float4*)&Bus[buf][k][tx * TN];
#pragma unroll
            for (int i = 0; i < TM; i++)
#pragma unroll
                for (int j = 0; j < TN; j++) {
                    accg[i][j] += ra[i] * rg[j];
                    accu[i][j] += ra[i] * ru[j];
                }
        }
#pragma unroll
        for (int i = 0; i < 2; i++) {
            float4 av = apre[i];
            av.x *= ascale[i]; av.y *= ascale[i]; av.z *= ascale[i]; av.w *= ascale[i];
            As[buf^1][akq[i]+0][arow[i]] = av.x; As[buf^1][akq[i]+1][arow[i]] = av.y;
            As[buf^1][akq[i]+2][arow[i]] = av.z; As[buf^1][akq[i]+3][arow[i]] = av.w;
            if (half == 0) *(float4*)&Bgs[buf^1][bk[i]][bcol[i]] = bpre[i];
            else           *(float4*)&Bus[buf^1][bk[i]][bcol[i]] = bpre[i];
        }
        __syncthreads();
    }
    {
        int buf = (nTiles - 1) & 1;
#pragma unroll
        for (int k = 0; k < BK; k++) {
            *(float4*)&ra[0] = *(const float4*)&As[buf][k][ty * TM];
            *(float4*)&ra[4] = *(const float4*)&As[buf][k][ty * TM + 4];
            *(float4*)&rg[0] = *(const float4*)&Bgs[buf][k][tx * TN];
            *(float4*)&ru[0] = *(const float4*)&Bus[buf][k][tx * TN];
#pragma unroll
            for (int i = 0; i < TM; i++)
#pragma unroll
                for (int j = 0; j < TN; j++) {
                    accg[i][j] += ra[i] * rg[j];
                    accu[i][j] += ra[i] * ru[j];
                }
        }
    }

#pragma unroll
    for (int i = 0; i < TM; i++) {
        int r = row0 + ty * TM + i;
        if (r >= seg_rows) break;
        size_t base = (size_t)r * N + col0 + tx * TN;
        float4 h;
        h.x = silu_f(accg[i][0]) * accu[i][0];
        h.y = silu_f(accg[i][1]) * accu[i][1];
        h.z = silu_f(accg[i][2]) * accu[i][2];
        h.w = silu_f(accg[i][3]) * accu[i][3];
        *(float4*)(Hseg + base) = h;
    }
}

// ---------------- merged down GEMM (z=0: g_H@ws_down -> out; z=1..NE: g_H2@w_down[e] -> g_O2 scattered) ----------------
// BM=128, BN=64, BK=16, 256 threads, 8x4 acc, double-buffered. Scatter rows are a bijection (top-1): plain stores.
__global__ void __launch_bounds__(256, 2)
gemm_down_all(float* __restrict__ out,
              const float* __restrict__ ws_down, const float* __restrict__ w_down) {
    const int BM = 128, BN = 64, BK = 16, TM = 8, TN = 4;
    const int LDA = BM + 4;
    const int K = F_DIM, N = D_DIM;

    int z = blockIdx.z;
    bool routed = (z > 0);
    int e = z - 1;
    int seg_start = 0, seg_rows = T_TOK;
    const float *A, *B;
    if (routed) {
        seg_start = g_offs[e]; seg_rows = g_offs[e + 1] - seg_start;
        A = g_H2 + (size_t)seg_start * K;
        B = w_down + (size_t)e * F_DIM * D_DIM;
    } else {
        A = g_H; B = ws_down;
    }
    int row0 = blockIdx.y * BM;
    if (row0 >= seg_rows) return;
    int col0 = blockIdx.x * BN;

    __shared__ float As[2][BK][LDA];
    __shared__ float Bs[2][BK][BN];

    int tid = threadIdx.x;
    int tx = tid & 15, ty = tid >> 4;

    int arow[2], akq[2]; const float* abase[2]; bool avalid[2];
#pragma unroll
    for (int i = 0; i < 2; i++) {
        int f4 = i * 256 + tid;
        arow[i] = f4 >> 2; akq[i] = (f4 & 3) * 4;
        int r = row0 + arow[i];
        avalid[i] = r < seg_rows;
        abase[i] = A + (size_t)(avalid[i] ? r : 0) * K + akq[i];
    }
    int bkk = tid >> 4, bcol = (tid & 15) * 4;
    const float* bbase = B + (size_t)bkk * N + col0 + bcol;

    float acc[TM][TN] = {};
    float ra[TM], rb[TN];
    const int nTiles = K / BK;

    {
#pragma unroll
        for (int i = 0; i < 2; i++) {
            float4 av = avalid[i] ? *(const float4*)abase[i] : make_float4(0.f,0.f,0.f,0.f);
            As[0][akq[i]+0][arow[i]] = av.x; As[0][akq[i]+1][arow[i]] = av.y;
            As[0][akq[i]+2][arow[i]] = av.z; As[0][akq[i]+3][arow[i]] = av.w;
        }
        *(float4*)&Bs[0][bkk][bcol] = *(const float4*)bbase;
    }
    __syncthreads();

    for (int tile = 0; tile < nTiles - 1; tile++) {
        int buf = tile & 1;
        float4 apre[2], bpre;
#pragma unroll
        for (int i = 0; i < 2; i++)
            apre[i] = avalid[i] ? *(const float4*)(abase[i] + (size_t)(tile + 1) * BK)
                                : make_float4(0.f,0.f,0.f,0.f);
        bpre = *(const float4*)(bbase + (size_t)(tile + 1) * BK * N);
#pragma unroll
        for (int k = 0; k < BK; k++) {
            *(float4*)&ra[0] = *(const float4*)&As[buf][k][ty * TM];
            *(float4*)&ra[4] = *(const float4*)&As[buf][k][ty * TM + 4];
            *(float4*)&rb[0] = *(const float4*)&Bs[buf][k][tx * TN];
#pragma unroll
            for (int i = 0; i < TM; i++)
#pragma unroll
                for (int j = 0; j < TN; j++) acc[i][j] += ra[i] * rb[j];
        }
#pragma unroll
        for (int i = 0; i < 2; i++) {
            As[buf^1][akq[i]+0][arow[i]] = apre[i].x; As[buf^1][akq[i]+1][arow[i]] = apre[i].y;
            As[buf^1][akq[i]+2][arow[i]] = apre[i].z; As[buf^1][akq[i]+3][arow[i]] = apre[i].w;
        }
        *(float4*)&Bs[buf^1][bkk][bcol] = bpre;
        __syncthreads();
    }
    {
        int buf = (nTiles - 1) & 1;
#pragma unroll
        for (int k = 0; k < BK; k++) {
            *(float4*)&ra[0] = *(const float4*)&As[buf][k][ty * TM];
            *(float4*)&ra[4] = *(const float4*)&As[buf][k][ty * TM + 4];
            *(float4*)&rb[0] = *(const float4*)&Bs[buf][k][tx * TN];
#pragma unroll
            for (int i = 0; i < TM; i++)
#pragma unroll
                for (int j = 0; j < TN; j++) acc[i][j] += ra[i] * rb[j];
        }
    }

#pragma unroll
    for (int i = 0; i < TM; i++) {
        int r = row0 + ty * TM + i;
        if (r >= seg_rows) break;
        float4 v = make_float4(acc[i][0], acc[i][1], acc[i][2], acc[i][3]);
        if (routed) {
            int tok = g_order[seg_start + r];
            *(float4*)(g_O2 + (size_t)tok * N + col0 + tx * TN) = v;
        } else {
            *(float4*)(out + (size_t)r * N + col0 + tx * TN) = v;
        }
    }
}

// ---------------- final add: out += g_O2 ----------------
__global__ void add_kernel(float* __restrict__ out) {
    size_t i = (size_t)blockIdx.x * 256 + threadIdx.x;       // T*D/4 = 524288 float4
    float4 v = ((float4*)out)[i];
    float4 w = ((const float4*)g_O2)[i];
    v.x += w.x; v.y += w.y; v.z += w.z; v.w += w.w;
    ((float4*)out)[i] = v;
}

extern "C" void kernel_launch(void* const* d_in, const int* in_sizes, int n_in,
                              void* d_out, int out_size) {
    const float* hidden   = (const float*)d_in[0];
    const float* router_w = (const float*)d_in[1];
    const float* w_gate   = (const float*)d_in[2];
    const float* w_up     = (const float*)d_in[3];
    const float* w_down   = (const float*)d_in[4];
    const float* ws_gate  = (const float*)d_in[5];
    const float* ws_up    = (const float*)d_in[6];
    const float* ws_down  = (const float*)d_in[7];
    float* out = (float*)d_out;

    // routing metadata (deterministic)
    router_kernel<<<T_TOK, 256>>>(hidden, router_w);
    rank_kernel<<<T_TOK / 256, 256>>>();
    offs_kernel<<<1, 256>>>();

    // gate+up for shared AND all experts in one full-chip launch
    dim3 gridGU(F_DIM / 64, T_TOK / 128, NE + 1);
    gemm_gateup_all<<<gridGU, 256>>>(hidden, ws_gate, ws_up, w_gate, w_up);

    // down for shared AND all experts in one full-chip launch (independent outputs)
    dim3 gridDN(D_DIM / 64, T_TOK / 128, NE + 1);
    gemm_down_all<<<gridDN, 256>>>(out, ws_down, w_down);

    // out += routed
    add_kernel<<<(T_TOK * D_DIM / 4) / 256, 256>>>(out);

    (void)in_sizes; (void)n_in; (void)out_size;
}

// round 7
// speedup vs baseline: 4.7705x; 1.8116x over previous
#include <cuda_runtime.h>
#include <cuda_bf16.h>
#include <math.h>

#define T_TOK 2048
#define D_DIM 1024
#define F_DIM 2048
#define NE 8

// ---- scratch: referenced ONLY inside device code (never passed as kernel args) ----
__device__ float g_H [(size_t)T_TOK * F_DIM];   // shared-expert silu(gate)*up (token order)
__device__ float g_H2[(size_t)T_TOK * F_DIM];   // routed silu(gate)*up (grouped order)
__device__ float g_O2[(size_t)T_TOK * D_DIM];   // routed down output (token order)
__device__ int   g_tok_e[T_TOK];
__device__ float g_tok_s[T_TOK];
__device__ int   g_order[T_TOK];                // grouped row -> token (bijection, top-1)
__device__ int   g_offs[NE + 1];

__device__ __forceinline__ float silu_f(float x) { return x / (1.0f + expf(-x)); }

// split fp32 pair into packed bf16 hi and lo planes (x0 in low 16 bits)
__device__ __forceinline__ void split2(float x0, float x1, unsigned &hi, unsigned &lo) {
    __nv_bfloat16 h0 = __float2bfloat16_rn(x0), h1 = __float2bfloat16_rn(x1);
    hi = (unsigned)__bfloat16_as_ushort(h0) | ((unsigned)__bfloat16_as_ushort(h1) << 16);
    float r0 = x0 - __bfloat162float(h0), r1 = x1 - __bfloat162float(h1);
    lo = (unsigned)__bfloat16_as_ushort(__float2bfloat16_rn(r0))
       | ((unsigned)__bfloat16_as_ushort(__float2bfloat16_rn(r1)) << 16);
}

__device__ __forceinline__ void ldsm4(unsigned r[4], const void* p) {
    unsigned a = (unsigned)__cvta_generic_to_shared(p);
    asm volatile("ldmatrix.sync.aligned.m8n8.x4.shared.b16 {%0,%1,%2,%3}, [%4];"
                 : "=r"(r[0]), "=r"(r[1]), "=r"(r[2]), "=r"(r[3]) : "r"(a));
}
__device__ __forceinline__ void ldsm4t(unsigned r[4], const void* p) {
    unsigned a = (unsigned)__cvta_generic_to_shared(p);
    asm volatile("ldmatrix.sync.aligned.m8n8.x4.trans.shared.b16 {%0,%1,%2,%3}, [%4];"
                 : "=r"(r[0]), "=r"(r[1]), "=r"(r[2]), "=r"(r[3]) : "r"(a));
}
__device__ __forceinline__ void mma_bf16(float c[4], const unsigned a[4], unsigned b0, unsigned b1) {
    asm volatile(
        "mma.sync.aligned.m16n8k16.row.col.f32.bf16.bf16.f32 "
        "{%0,%1,%2,%3}, {%4,%5,%6,%7}, {%8,%9}, {%0,%1,%2,%3};"
        : "+f"(c[0]), "+f"(c[1]), "+f"(c[2]), "+f"(c[3])
        : "r"(a[0]), "r"(a[1]), "r"(a[2]), "r"(a[3]), "r"(b0), "r"(b1));
}

// ---------------- router: one block per token, coalesced, deterministic ----------------
__global__ void router_kernel(const float* __restrict__ x, const float* __restrict__ rw) {
    __shared__ float red[256][NE + 1];
    int t = blockIdx.x, tid = threadIdx.x;
    float4 xa = ((const float4*)(x + (size_t)t * D_DIM))[tid];
#pragma unroll
    for (int e = 0; e < NE; e++) {
        float4 wv = ((const float4*)(rw + (size_t)e * D_DIM))[tid];
        red[tid][e] = xa.x * wv.x + xa.y * wv.y + xa.z * wv.z + xa.w * wv.w;
    }
    __syncthreads();
    for (int s = 128; s > 0; s >>= 1) {
        if (tid < s)
#pragma unroll
            for (int e = 0; e < NE; e++) red[tid][e] += red[tid + s][e];
        __syncthreads();
    }
    if (tid == 0) {
        float bv = red[0][0]; int be = 0;
#pragma unroll
        for (int e = 1; e < NE; e++) if (red[0][e] > bv) { bv = red[0][e]; be = e; }
        g_tok_e[t] = be;
        g_tok_s[t] = 1.0f / (1.0f + expf(-bv));
    }
}

// ---------------- stable rank + offsets via smem-cached brute force ----------------
__global__ void rank_kernel() {
    __shared__ int s_e[T_TOK];
    int tid = threadIdx.x;
    for (int i = tid; i < T_TOK; i += 256) s_e[i] = g_tok_e[i];
    __syncthreads();
    int t = blockIdx.x * 256 + tid;
    int e = s_e[t];
    int r = 0;
#pragma unroll 4
    for (int u = 0; u < T_TOK; u++) {
        int eu = s_e[u];
        r += (eu < e) || (eu == e && u < t);
    }
    g_order[r] = t;
}

__global__ void offs_kernel() {
    __shared__ int s_e[T_TOK];
    int tid = threadIdx.x;
    for (int i = tid; i < T_TOK; i += 256) s_e[i] = g_tok_e[i];
    __syncthreads();
    if (tid <= NE) {
        int c = 0;
#pragma unroll 4
        for (int u = 0; u < T_TOK; u++) c += (s_e[u] < tid);
        g_offs[tid] = c;
    }
}

// ================= split-bf16 tensor-core gate+up GEMM =================
// Block 128m x 64n, BK=16, 8 warps as 4(m) x 2(n); warp tile 32m x 32n for BOTH gate and up.
// z=0: shared expert -> g_H ; z=1..NE: routed (gathered+scaled rows) -> g_H2.
__global__ void __launch_bounds__(256, 2)
gemm_gateup_all(const float* __restrict__ X,
                const float* __restrict__ ws_gate, const float* __restrict__ ws_up,
                const float* __restrict__ w_gate,  const float* __restrict__ w_up) {
    const int BM = 128, BK = 16;
    const int LDA = 24, LDB = 72;          // bf16 strides, ldmatrix-conflict-free, 16B-aligned
    const int K = D_DIM, N = F_DIM;

    int z = blockIdx.z;
    bool gather = (z > 0);
    int e = z - 1;
    int seg_start = 0, seg_rows = T_TOK;
    const float *Bg, *Bu; float* Hseg;
    if (gather) {
        seg_start = g_offs[e]; seg_rows = g_offs[e + 1] - seg_start;
        Bg = w_gate + (size_t)e * D_DIM * F_DIM;
        Bu = w_up   + (size_t)e * D_DIM * F_DIM;
        Hseg = g_H2 + (size_t)seg_start * N;
    } else {
        Bg = ws_gate; Bu = ws_up; Hseg = g_H;
    }
    int row0 = blockIdx.y * BM;
    if (row0 >= seg_rows) return;
    int col0 = blockIdx.x * 64;

    __shared__ __align__(16) __nv_bfloat16 sAh[2][BM * LDA], sAl[2][BM * LDA];
    __shared__ __align__(16) __nv_bfloat16 sGh[2][BK * LDB], sGl[2][BK * LDB];
    __shared__ __align__(16) __nv_bfloat16 sUh[2][BK * LDB], sUl[2][BK * LDB];

    int tid = threadIdx.x, lane = tid & 31, wid = tid >> 5;
    int wm = wid & 3, wn = wid >> 2;

    // A: 128 rows x 16 k fp32 = 512 float4; 2 per thread
    int ar[2], ak[2]; const float* ap[2]; float asc[2]; bool av[2];
#pragma unroll
    for (int i = 0; i < 2; i++) {
        int f4 = i * 256 + tid;
        ar[i] = f4 >> 2; ak[i] = (f4 & 3) * 4;
        int r = row0 + ar[i];
        av[i] = r < seg_rows;
        if (gather) {
            int tok = av[i] ? g_order[seg_start + r] : 0;
            asc[i] = av[i] ? g_tok_s[tok] : 0.0f;
            ap[i] = X + (size_t)tok * K + ak[i];
        } else {
            asc[i] = 1.0f;
            ap[i] = X + (size_t)(av[i] ? r : 0) * K + ak[i];
        }
    }
    // B: 16 x 64 fp32 per matrix = 256 float4; 1 per thread per matrix
    int bkr = tid >> 4, bcc = (tid & 15) * 4;
    const float* gp = Bg + (size_t)bkr * N + col0 + bcc;
    const float* up = Bu + (size_t)bkr * N + col0 + bcc;

    float accg[2][4][4] = {}, accu[2][4][4] = {};

    auto stage = [&](int buf, const float4 a[2], float4 gv, float4 uv) {
#pragma unroll
        for (int i = 0; i < 2; i++) {
            float4 v = a[i];
            v.x *= asc[i]; v.y *= asc[i]; v.z *= asc[i]; v.w *= asc[i];
            unsigned h0, l0, h1, l1;
            split2(v.x, v.y, h0, l0); split2(v.z, v.w, h1, l1);
            int off = ar[i] * LDA + ak[i];
            *(unsigned*)&sAh[buf][off] = h0; *(unsigned*)&sAh[buf][off + 2] = h1;
            *(unsigned*)&sAl[buf][off] = l0; *(unsigned*)&sAl[buf][off + 2] = l1;
        }
        {
            unsigned h0, l0, h1, l1;
            int off = bkr * LDB + bcc;
            split2(gv.x, gv.y, h0, l0); split2(gv.z, gv.w, h1, l1);
            *(unsigned*)&sGh[buf][off] = h0; *(unsigned*)&sGh[buf][off + 2] = h1;
            *(unsigned*)&sGl[buf][off] = l0; *(unsigned*)&sGl[buf][off + 2] = l1;
            split2(uv.x, uv.y, h0, l0); split2(uv.z, uv.w, h1, l1);
            *(unsigned*)&sUh[buf][off] = h0; *(unsigned*)&sUh[buf][off + 2] = h1;
            *(unsigned*)&sUl[buf][off] = l0; *(unsigned*)&sUl[buf][off + 2] = l1;
        }
    };

    auto compute = [&](int buf) {
        unsigned ah[2][4], al[2][4];
#pragma unroll
        for (int mt = 0; mt < 2; mt++) {
            int r = wm * 32 + mt * 16 + (lane & 15);
            int kk = (lane >> 4) * 8;
            ldsm4(ah[mt], &sAh[buf][r * LDA + kk]);
            ldsm4(al[mt], &sAl[buf][r * LDA + kk]);
        }
#pragma unroll
        for (int h = 0; h < 2; h++) {
            int krow = lane & 15;
            int nof = wn * 32 + h * 16 + (lane >> 4) * 8;
            unsigned gh[4], gl[4], uh[4], ul[4];
            ldsm4t(gh, &sGh[buf][krow * LDB + nof]);
            ldsm4t(gl, &sGl[buf][krow * LDB + nof]);
            ldsm4t(uh, &sUh[buf][krow * LDB + nof]);
            ldsm4t(ul, &sUl[buf][krow * LDB + nof]);
#pragma unroll
            for (int mt = 0; mt < 2; mt++)
#pragma unroll
                for (int nn = 0; nn < 2; nn++) {
                    float* cg = accg[mt][h * 2 + nn];
                    float* cu = accu[mt][h * 2 + nn];
                    mma_bf16(cg, ah[mt], gh[2*nn], gh[2*nn+1]);
                    mma_bf16(cg, ah[mt], gl[2*nn], gl[2*nn+1]);
                    mma_bf16(cg, al[mt], gh[2*nn], gh[2*nn+1]);
                    mma_bf16(cu, ah[mt], uh[2*nn], uh[2*nn+1]);
                    mma_bf16(cu, ah[mt], ul[2*nn], ul[2*nn+1]);
                    mma_bf16(cu, al[mt], uh[2*nn], uh[2*nn+1]);
                }
        }
    };

    const int nT = K / BK;
    {   // prologue
        float4 a[2] = {
            av[0] ? *(const float4*)ap[0] : make_float4(0,0,0,0),
            av[1] ? *(const float4*)ap[1] : make_float4(0,0,0,0) };
        stage(0, a, *(const float4*)gp, *(const float4*)up);
    }
    __syncthreads();

    for (int t = 0; t < nT - 1; t++) {
        int buf = t & 1;
        float4 an[2], gn, un;
#pragma unroll
        for (int i = 0; i < 2; i++)
            an[i] = av[i] ? *(const float4*)(ap[i] + (size_t)(t + 1) * BK) : make_float4(0,0,0,0);
        gn = *(const float4*)(gp + (size_t)(t + 1) * BK * N);
        un = *(const float4*)(up + (size_t)(t + 1) * BK * N);
        compute(buf);
        stage(buf ^ 1, an, gn, un);
        __syncthreads();
    }
    compute((nT - 1) & 1);

    // epilogue: H = silu(g) * u
#pragma unroll
    for (int mt = 0; mt < 2; mt++)
#pragma unroll
        for (int nn = 0; nn < 4; nn++) {
            int r0 = row0 + wm * 32 + mt * 16 + (lane >> 2);
            int c = col0 + wn * 32 + nn * 8 + (lane & 3) * 2;
            float* cg = accg[mt][nn]; float* cu = accu[mt][nn];
            if (r0 < seg_rows) {
                float2 v = { silu_f(cg[0]) * cu[0], silu_f(cg[1]) * cu[1] };
                *(float2*)&Hseg[(size_t)r0 * N + c] = v;
            }
            int r1 = r0 + 8;
            if (r1 < seg_rows) {
                float2 v = { silu_f(cg[2]) * cu[2], silu_f(cg[3]) * cu[3] };
                *(float2*)&Hseg[(size_t)r1 * N + c] = v;
            }
        }
}

// ================= split-bf16 tensor-core down GEMM =================
// Block 128m x 128n, BK=16, 8 warps 4(m) x 2(n); warp tile 32m x 64n.
// z=0: g_H @ ws_down -> out ; z=1..NE: g_H2 seg @ w_down[e] -> g_O2 (scattered rows).
__global__ void __launch_bounds__(256, 2)
gemm_down_all(float* __restrict__ out,
              const float* __restrict__ ws_down, const float* __restrict__ w_down) {
    const int BM = 128, BK = 16;
    const int LDA = 24, LDB = 136;
    const int K = F_DIM, N = D_DIM;

    int z = blockIdx.z;
    bool routed = (z > 0);
    int e = z - 1;
    int seg_start = 0, seg_rows = T_TOK;
    const float *A, *B;
    if (routed) {
        seg_start = g_offs[e]; seg_rows = g_offs[e + 1] - seg_start;
        A = g_H2 + (size_t)seg_start * K;
        B = w_down + (size_t)e * F_DIM * D_DIM;
    } else {
        A = g_H; B = ws_down;
    }
    int row0 = blockIdx.y * BM;
    if (row0 >= seg_rows) return;
    int col0 = blockIdx.x * 128;

    __shared__ __align__(16) __nv_bfloat16 sAh[2][BM * LDA], sAl[2][BM * LDA];
    __shared__ __align__(16) __nv_bfloat16 sBh[2][BK * LDB], sBl[2][BK * LDB];

    int tid = threadIdx.x, lane = tid & 31, wid = tid >> 5;
    int wm = wid & 3, wn = wid >> 2;

    int ar[2], ak[2]; const float* ap[2]; bool av[2];
#pragma unroll
    for (int i = 0; i < 2; i++) {
        int f4 = i * 256 + tid;
        ar[i] = f4 >> 2; ak[i] = (f4 & 3) * 4;
        int r = row0 + ar[i];
        av[i] = r < seg_rows;
        ap[i] = A + (size_t)(av[i] ? r : 0) * K + ak[i];
    }
    // B: 16 x 128 fp32 = 512 float4; 2 per thread
    int bkr[2], bcc[2]; const float* bp[2];
#pragma unroll
    for (int i = 0; i < 2; i++) {
        int f4 = i * 256 + tid;
        bkr[i] = f4 >> 5; bcc[i] = (f4 & 31) * 4;
        bp[i] = B + (size_t)bkr[i] * N + col0 + bcc[i];
    }

    float acc[2][8][4] = {};

    auto stage = [&](int buf, const float4 a[2], const float4 b[2]) {
#pragma unroll
        for (int i = 0; i < 2; i++) {
            unsigned h0, l0, h1, l1;
            split2(a[i].x, a[i].y, h0, l0); split2(a[i].z, a[i].w, h1, l1);
            int off = ar[i] * LDA + ak[i];
            *(unsigned*)&sAh[buf][off] = h0; *(unsigned*)&sAh[buf][off + 2] = h1;
            *(unsigned*)&sAl[buf][off] = l0; *(unsigned*)&sAl[buf][off + 2] = l1;
            split2(b[i].x, b[i].y, h0, l0); split2(b[i].z, b[i].w, h1, l1);
            off = bkr[i] * LDB + bcc[i];
            *(unsigned*)&sBh[buf][off] = h0; *(unsigned*)&sBh[buf][off + 2] = h1;
            *(unsigned*)&sBl[buf][off] = l0; *(unsigned*)&sBl[buf][off + 2] = l1;
        }
    };

    auto compute = [&](int buf) {
        unsigned ah[2][4], al[2][4];
#pragma unroll
        for (int mt = 0; mt < 2; mt++) {
            int r = wm * 32 + mt * 16 + (lane & 15);
            int kk = (lane >> 4) * 8;
            ldsm4(ah[mt], &sAh[buf][r * LDA + kk]);
            ldsm4(al[mt], &sAl[buf][r * LDA + kk]);
        }
#pragma unroll
        for (int h = 0; h < 4; h++) {
            int krow = lane & 15;
            int nof = wn * 64 + h * 16 + (lane >> 4) * 8;
            unsigned bh[4], bl[4];
            ldsm4t(bh, &sBh[buf][krow * LDB + nof]);
            ldsm4t(bl, &sBl[buf][krow * LDB + nof]);
#pragma unroll
            for (int mt = 0; mt < 2; mt++)
#pragma unroll
                for (int nn = 0; nn < 2; nn++) {
                    float* c = acc[mt][h * 2 + nn];
                    mma_bf16(c, ah[mt], bh[2*nn], bh[2*nn+1]);
                    mma_bf16(c, ah[mt], bl[2*nn], bl[2*nn+1]);
                    mma_bf16(c, al[mt], bh[2*nn], bh[2*nn+1]);
                }
        }
    };

    const int nT = K / BK;
    {
        float4 a[2] = {
            av[0] ? *(const float4*)ap[0] : make_float4(0,0,0,0),
            av[1] ? *(const float4*)ap[1] : make_float4(0,0,0,0) };
        float4 b[2] = { *(const float4*)bp[0], *(const float4*)bp[1] };
        stage(0, a, b);
    }
    __syncthreads();

    for (int t = 0; t < nT - 1; t++) {
        int buf = t & 1;
        float4 an[2], bn[2];
#pragma unroll
        for (int i = 0; i < 2; i++) {
            an[i] = av[i] ? *(const float4*)(ap[i] + (size_t)(t + 1) * BK) : make_float4(0,0,0,0);
            bn[i] = *(const float4*)(bp[i] + (size_t)(t + 1) * BK * N);
        }
        compute(buf);
        stage(buf ^ 1, an, bn);
        __syncthreads();
    }
    compute((nT - 1) & 1);

    // epilogue
#pragma unroll
    for (int mt = 0; mt < 2; mt++) {
        int rb0 = row0 + wm * 32 + mt * 16 + (lane >> 2);
        int rb1 = rb0 + 8;
        int tok0 = -1, tok1 = -1;
        if (rb0 < seg_rows) tok0 = routed ? g_order[seg_start + rb0] : rb0;
        if (rb1 < seg_rows) tok1 = routed ? g_order[seg_start + rb1] : rb1;
        float* dst = routed ? g_O2 : out;
#pragma unroll
        for (int nn = 0; nn < 8; nn++) {
            int c = col0 + wn * 64 + nn * 8 + (lane & 3) * 2;
            float* cc = acc[mt][nn];
            if (tok0 >= 0) { float2 v = { cc[0], cc[1] }; *(float2*)&dst[(size_t)tok0 * N + c] = v; }
            if (tok1 >= 0) { float2 v = { cc[2], cc[3] }; *(float2*)&dst[(size_t)tok1 * N + c] = v; }
        }
    }
}

// ---------------- final add: out += g_O2 ----------------
__global__ void add_kernel(float* __restrict__ out) {
    size_t i = (size_t)blockIdx.x * 256 + threadIdx.x;
    float4 v = ((float4*)out)[i];
    float4 w = ((const float4*)g_O2)[i];
    v.x += w.x; v.y += w.y; v.z += w.z; v.w += w.w;
    ((float4*)out)[i] = v;
}

extern "C" void kernel_launch(void* const* d_in, const int* in_sizes, int n_in,
                              void* d_out, int out_size) {
    const float* hidden   = (const float*)d_in[0];
    const float* router_w = (const float*)d_in[1];
    const float* w_gate   = (const float*)d_in[2];
    const float* w_up     = (const float*)d_in[3];
    const float* w_down   = (const float*)d_in[4];
    const float* ws_gate  = (const float*)d_in[5];
    const float* ws_up    = (const float*)d_in[6];
    const float* ws_down  = (const float*)d_in[7];
    float* out = (float*)d_out;

    router_kernel<<<T_TOK, 256>>>(hidden, router_w);
    rank_kernel<<<T_TOK / 256, 256>>>();
    offs_kernel<<<1, 256>>>();

    dim3 gridGU(F_DIM / 64, T_TOK / 128, NE + 1);
    gemm_gateup_all<<<gridGU, 256>>>(hidden, ws_gate, ws_up, w_gate, w_up);

    dim3 gridDN(D_DIM / 128, T_TOK / 128, NE + 1);
    gemm_down_all<<<gridDN, 256>>>(out, ws_down, w_down);

    add_kernel<<<(T_TOK * D_DIM / 4) / 256, 256>>>(out);

    (void)in_sizes; (void)n_in; (void)out_size;
}